// round 5
// baseline (speedup 1.0000x reference)
#include <cuda_runtime.h>
#include <cuda_bf16.h>
#include <cstdint>

constexpr int NA = 1024, NB = 1024, DD = 512, KK = 256;

// Device scratch
__device__ __nv_bfloat16 g_Ph[NA * KK];
__device__ __nv_bfloat16 g_Mb[NB * KK];

// ---------------------------------------------------------------------------
// PTX helpers (sm_80+ family-safe)
// ---------------------------------------------------------------------------
__device__ __forceinline__ uint32_t smem_u32(const void* p) {
    uint32_t r;
    asm("{ .reg .u64 t; cvta.to.shared.u64 t, %1; cvt.u32.u64 %0, t; }" : "=r"(r) : "l"(p));
    return r;
}
__device__ __forceinline__ void cp16(uint32_t dst, const void* src) {
    asm volatile("cp.async.cg.shared.global [%0], [%1], 16;" :: "r"(dst), "l"(src) : "memory");
}
__device__ __forceinline__ void cp_commit() { asm volatile("cp.async.commit_group;" ::: "memory"); }
__device__ __forceinline__ void cp_wait0()  { asm volatile("cp.async.wait_group 0;" ::: "memory"); }

__device__ __forceinline__ void ldm_x4(uint32_t* r, uint32_t addr) {
    asm volatile("ldmatrix.sync.aligned.m8n8.x4.shared.b16 {%0,%1,%2,%3}, [%4];"
                 : "=r"(r[0]), "=r"(r[1]), "=r"(r[2]), "=r"(r[3]) : "r"(addr));
}
__device__ __forceinline__ void mma_bf16(float* d, const uint32_t* a, const uint32_t* b) {
    asm volatile(
        "mma.sync.aligned.m16n8k16.row.col.f32.bf16.bf16.f32 "
        "{%0,%1,%2,%3}, {%4,%5,%6,%7}, {%8,%9}, {%0,%1,%2,%3};"
        : "+f"(d[0]), "+f"(d[1]), "+f"(d[2]), "+f"(d[3])
        : "r"(a[0]), "r"(a[1]), "r"(a[2]), "r"(a[3]), "r"(b[0]), "r"(b[1]));
}

// ldmatrix addressing, parametric row stride (bytes)
__device__ __forceinline__ uint32_t a_addr(uint32_t base, int row0, int lane, int koff, uint32_t stride) {
    return base + (uint32_t)(row0 + (lane & 15)) * stride + (uint32_t)koff + ((lane >> 4) << 4);
}
__device__ __forceinline__ uint32_t b_addr(uint32_t base, int row0, int lane, int koff, uint32_t stride) {
    return base + (uint32_t)(row0 + (lane & 7) + ((lane >> 4) << 3)) * stride
                + (uint32_t)koff + (((lane >> 3) & 1) << 4);
}

// pack float4 -> (hi uint2, lo uint2) bf16 pairs
__device__ __forceinline__ void split_pack(const float4& v, uint2& h, uint2& l) {
    float xs[4] = {v.x, v.y, v.z, v.w};
    __nv_bfloat16 hs[4], ls[4];
#pragma unroll
    for (int i = 0; i < 4; i++) {
        hs[i] = __float2bfloat16(xs[i]);
        ls[i] = __float2bfloat16(xs[i] - __bfloat162float(hs[i]));
    }
    __nv_bfloat162 h01(hs[0], hs[1]), h23(hs[2], hs[3]);
    __nv_bfloat162 l01(ls[0], ls[1]), l23(ls[2], ls[3]);
    h.x = *reinterpret_cast<uint32_t*>(&h01); h.y = *reinterpret_cast<uint32_t*>(&h23);
    l.x = *reinterpret_cast<uint32_t*>(&l01); l.y = *reinterpret_cast<uint32_t*>(&l23);
}

// ---------------------------------------------------------------------------
// Stage 1 (fused convert): C[2048x256] = X · F^T  (AhFh + AhFl + AlFh)
// Tile 64x64, k-chunks of 32. grid (4, 32), 256 threads.
// ONE __syncthreads per chunk; LDG prefetch distance 2.
// ---------------------------------------------------------------------------
constexpr uint32_t S1STR = 80;      // 32 bf16 = 64B data, padded to 80B
constexpr uint32_t S1_XH = 0;
constexpr uint32_t S1_XL = 5120;
constexpr uint32_t S1_FH = 10240;
constexpr uint32_t S1_FL = 15360;
constexpr uint32_t S1_BUF = 20480;
constexpr int S1_SMEM = 40960;

__global__ __launch_bounds__(256) void stage1_mma(
    const float* __restrict__ a, const float* __restrict__ b, const float* __restrict__ feats)
{
    extern __shared__ char dsm[];
    const uint32_t sb = smem_u32(dsm);

    const int tid = threadIdx.x;
    const int lane = tid & 31;
    const int wid = tid >> 5;
    const int wm = wid & 1;          // 2 warp rows x 32
    const int wn = wid >> 1;         // 4 warp cols x 16

    const int m0 = blockIdx.y * 64;
    const int n0 = blockIdx.x * 64;
    const bool isA = (m0 < NA);
    const float* __restrict__ Xf = (isA ? a + (size_t)m0 * DD
                                        : b + (size_t)(m0 - NA) * DD);
    const float* __restrict__ Ff = feats + (size_t)n0 * DD;

    const int r0 = tid >> 3, s0 = tid & 7;
    const int r1 = r0 + 32;

    float4 rx[2][2], rf[2][2];
    auto ldg_chunk = [&](int ch, int set) {
        const int d0 = ch * 32;
        rx[set][0] = *reinterpret_cast<const float4*>(Xf + (size_t)r0 * DD + d0 + s0 * 4);
        rx[set][1] = *reinterpret_cast<const float4*>(Xf + (size_t)r1 * DD + d0 + s0 * 4);
        rf[set][0] = *reinterpret_cast<const float4*>(Ff + (size_t)r0 * DD + d0 + s0 * 4);
        rf[set][1] = *reinterpret_cast<const float4*>(Ff + (size_t)r1 * DD + d0 + s0 * 4);
    };
    auto sts_chunk = [&](int set, uint32_t bb) {
        char* bp = dsm + (bb - sb);
        const uint32_t off0 = (uint32_t)r0 * S1STR + (uint32_t)(s0 << 3);
        const uint32_t off1 = (uint32_t)r1 * S1STR + (uint32_t)(s0 << 3);
        uint2 h, l;
        split_pack(rx[set][0], h, l);
        *reinterpret_cast<uint2*>(bp + S1_XH + off0) = h;
        *reinterpret_cast<uint2*>(bp + S1_XL + off0) = l;
        split_pack(rx[set][1], h, l);
        *reinterpret_cast<uint2*>(bp + S1_XH + off1) = h;
        *reinterpret_cast<uint2*>(bp + S1_XL + off1) = l;
        split_pack(rf[set][0], h, l);
        *reinterpret_cast<uint2*>(bp + S1_FH + off0) = h;
        *reinterpret_cast<uint2*>(bp + S1_FL + off0) = l;
        split_pack(rf[set][1], h, l);
        *reinterpret_cast<uint2*>(bp + S1_FH + off1) = h;
        *reinterpret_cast<uint2*>(bp + S1_FL + off1) = l;
    };

    float acc[2][2][4] = {};
    constexpr int NCH = DD / 32;   // 16

    ldg_chunk(0, 0);
    sts_chunk(0, sb);
    ldg_chunk(1, 1);

    for (int ch = 0; ch < NCH; ch++) {
        __syncthreads();   // buf[ch&1] filled; all reads of buf[(ch+1)&1] (iter ch-1) done
        if (ch + 1 < NCH) sts_chunk((ch + 1) & 1, sb + (uint32_t)((ch + 1) & 1) * S1_BUF);
        if (ch + 2 < NCH) ldg_chunk(ch + 2, ch & 1);

        const uint32_t bb = sb + (uint32_t)(ch & 1) * S1_BUF;
#pragma unroll
        for (int ks = 0; ks < 2; ks++) {
            const int koff = ks * 32;
            uint32_t ah[2][4], al[2][4], fh[4], fl[4];
#pragma unroll
            for (int mt = 0; mt < 2; mt++) {
                ldm_x4(ah[mt], a_addr(bb + S1_XH, wm * 32 + mt * 16, lane, koff, S1STR));
                ldm_x4(al[mt], a_addr(bb + S1_XL, wm * 32 + mt * 16, lane, koff, S1STR));
            }
            ldm_x4(fh, b_addr(bb + S1_FH, wn * 16, lane, koff, S1STR));
            ldm_x4(fl, b_addr(bb + S1_FL, wn * 16, lane, koff, S1STR));
#pragma unroll
            for (int mt = 0; mt < 2; mt++)
#pragma unroll
                for (int nt = 0; nt < 2; nt++) {
                    mma_bf16(acc[mt][nt], ah[mt], &fh[nt * 2]);
                    mma_bf16(acc[mt][nt], ah[mt], &fl[nt * 2]);
                    mma_bf16(acc[mt][nt], al[mt], &fh[nt * 2]);
                }
        }
    }

    // Epilogue: Ph = bf16(relu(v)) for a-rows; Mb = (v<=0) for b-rows
#pragma unroll
    for (int mt = 0; mt < 2; mt++)
#pragma unroll
        for (int nt = 0; nt < 2; nt++)
#pragma unroll
            for (int h = 0; h < 2; h++) {
                const int grow = m0 + wm * 32 + mt * 16 + (lane >> 2) + h * 8;
                const int col  = n0 + wn * 16 + nt * 8 + (lane & 3) * 2;
                const float v0 = acc[mt][nt][h * 2 + 0];
                const float v1 = acc[mt][nt][h * 2 + 1];
                if (isA) {
                    const size_t idx = (size_t)grow * KK + col;
                    *reinterpret_cast<__nv_bfloat162*>(g_Ph + idx) = __nv_bfloat162(
                        __float2bfloat16(fmaxf(v0, 0.0f)), __float2bfloat16(fmaxf(v1, 0.0f)));
                } else {
                    const size_t idx = (size_t)(grow - NA) * KK + col;
                    *reinterpret_cast<__nv_bfloat162*>(g_Mb + idx) = __nv_bfloat162(
                        __float2bfloat16(v0 <= 0.0f ? 1.0f : 0.0f),
                        __float2bfloat16(v1 <= 0.0f ? 1.0f : 0.0f));
                }
            }
}

// ---------------------------------------------------------------------------
// Stage 2 (monolithic K): out[1024x1024] = Ph · Mb^T
// Tile 64(M) x 128(N), FULL K=256 in smem, one sync, grid (8, 16), 256 thr.
// ---------------------------------------------------------------------------
constexpr uint32_t S2STR = 528;                 // 256 bf16 = 512B + 16B pad
constexpr uint32_t S2_PH = 0;
constexpr uint32_t S2_MB = 64 * S2STR;          // 33792
constexpr int S2_SMEM = 64 * 528 + 128 * 528;   // 101376

__global__ __launch_bounds__(256) void stage2_mma(float* __restrict__ out)
{
    extern __shared__ char dsm[];
    const uint32_t sb = smem_u32(dsm);

    const int tid = threadIdx.x;
    const int lane = tid & 31;
    const int wid = tid >> 5;
    const int wm = wid & 1;          // 2 warp rows x 32
    const int wn = wid >> 1;         // 4 warp cols x 32

    const int i0 = blockIdx.y * 64;
    const int j0 = blockIdx.x * 128;

    // Load everything: Ph 64x256 (2048 x 16B), Mb 128x256 (4096 x 16B)
    for (int v = tid; v < 6144; v += 256) {
        if (v < 2048) {
            const int r = v >> 5, s = v & 31;
            cp16(sb + S2_PH + (uint32_t)r * S2STR + (uint32_t)(s << 4),
                 g_Ph + (size_t)(i0 + r) * KK + s * 8);
        } else {
            const int w = v - 2048, r = w >> 5, s = w & 31;
            cp16(sb + S2_MB + (uint32_t)r * S2STR + (uint32_t)(s << 4),
                 g_Mb + (size_t)(j0 + r) * KK + s * 8);
        }
    }
    cp_commit();
    cp_wait0();
    __syncthreads();

    float acc[2][4][4] = {};

#pragma unroll
    for (int kc = 0; kc < KK / 16; kc++) {      // 16 chunks, straight-line
        const int kb = kc * 32;
        uint32_t ph[2][4], mb[2][4];
#pragma unroll
        for (int mt = 0; mt < 2; mt++)
            ldm_x4(ph[mt], a_addr(sb + S2_PH, wm * 32 + mt * 16, lane, kb, S2STR));
#pragma unroll
        for (int p = 0; p < 2; p++)
            ldm_x4(mb[p], b_addr(sb + S2_MB, wn * 32 + p * 16, lane, kb, S2STR));
#pragma unroll
        for (int mt = 0; mt < 2; mt++)
#pragma unroll
            for (int nt = 0; nt < 4; nt++)
                mma_bf16(acc[mt][nt], ph[mt], &mb[nt >> 1][(nt & 1) * 2]);
    }

#pragma unroll
    for (int mt = 0; mt < 2; mt++)
#pragma unroll
        for (int nt = 0; nt < 4; nt++)
#pragma unroll
            for (int h = 0; h < 2; h++) {
                const int row = i0 + wm * 32 + mt * 16 + (lane >> 2) + h * 8;
                const int col = j0 + wn * 32 + nt * 8 + (lane & 3) * 2;
                *reinterpret_cast<float2*>(out + (size_t)row * NB + col) =
                    make_float2(acc[mt][nt][h * 2 + 0], acc[mt][nt][h * 2 + 1]);
            }
}

// ---------------------------------------------------------------------------
extern "C" void kernel_launch(void* const* d_in, const int* in_sizes, int n_in,
                              void* d_out, int out_size)
{
    const float* a     = (const float*)d_in[0];
    const float* b     = (const float*)d_in[1];
    const float* feats = (const float*)d_in[2];
    float* out = (float*)d_out;
    (void)in_sizes; (void)n_in; (void)out_size;

    cudaFuncSetAttribute(stage2_mma, cudaFuncAttributeMaxDynamicSharedMemorySize, S2_SMEM);

    stage1_mma<<<dim3(4, 32), 256, S1_SMEM>>>(a, b, feats);
    stage2_mma<<<dim3(8, 16), 256, S2_SMEM>>>(out);
}

// round 6
// speedup vs baseline: 1.4307x; 1.4307x over previous
#include <cuda_runtime.h>
#include <cuda_bf16.h>
#include <cuda_fp16.h>
#include <cstdint>

constexpr int NA = 1024, NB = 1024, DD = 512, KK = 256;
constexpr int XROWS = NA + NB;

// Device scratch
__device__ __nv_bfloat16 g_Xh[XROWS * DD];
__device__ __nv_bfloat16 g_Xl[XROWS * DD];
__device__ __nv_bfloat16 g_Fh[KK * DD];
__device__ __nv_bfloat16 g_Fl[KK * DD];
__device__ __half        g_Ph[NA * KK];
__device__ __half        g_Mb[NB * KK];

// ---------------------------------------------------------------------------
// PTX helpers
// ---------------------------------------------------------------------------
__device__ __forceinline__ uint32_t smem_u32(const void* p) {
    uint32_t r;
    asm("{ .reg .u64 t; cvta.to.shared.u64 t, %1; cvt.u32.u64 %0, t; }" : "=r"(r) : "l"(p));
    return r;
}
__device__ __forceinline__ void cp16(uint32_t dst, const void* src) {
    asm volatile("cp.async.cg.shared.global [%0], [%1], 16;" :: "r"(dst), "l"(src) : "memory");
}
__device__ __forceinline__ void cp_commit() { asm volatile("cp.async.commit_group;" ::: "memory"); }
__device__ __forceinline__ void cp_wait1()  { asm volatile("cp.async.wait_group 1;" ::: "memory"); }
__device__ __forceinline__ void cp_wait0()  { asm volatile("cp.async.wait_group 0;" ::: "memory"); }

__device__ __forceinline__ void ldm_x4(uint32_t* r, uint32_t addr) {
    asm volatile("ldmatrix.sync.aligned.m8n8.x4.shared.b16 {%0,%1,%2,%3}, [%4];"
                 : "=r"(r[0]), "=r"(r[1]), "=r"(r[2]), "=r"(r[3]) : "r"(addr));
}
__device__ __forceinline__ void mma_bf16(float* d, const uint32_t* a, const uint32_t* b) {
    asm volatile(
        "mma.sync.aligned.m16n8k16.row.col.f32.bf16.bf16.f32 "
        "{%0,%1,%2,%3}, {%4,%5,%6,%7}, {%8,%9}, {%0,%1,%2,%3};"
        : "+f"(d[0]), "+f"(d[1]), "+f"(d[2]), "+f"(d[3])
        : "r"(a[0]), "r"(a[1]), "r"(a[2]), "r"(a[3]), "r"(b[0]), "r"(b[1]));
}
__device__ __forceinline__ void mma_f16(float* d, const uint32_t* a, const uint32_t* b) {
    asm volatile(
        "mma.sync.aligned.m16n8k16.row.col.f32.f16.f16.f32 "
        "{%0,%1,%2,%3}, {%4,%5,%6,%7}, {%8,%9}, {%0,%1,%2,%3};"
        : "+f"(d[0]), "+f"(d[1]), "+f"(d[2]), "+f"(d[3])
        : "r"(a[0]), "r"(a[1]), "r"(a[2]), "r"(a[3]), "r"(b[0]), "r"(b[1]));
}

// row stride 144B: consecutive rows shift 16B mod 128 -> ldmatrix conflict-free
constexpr uint32_t TSTR = 144;

__device__ __forceinline__ uint32_t a_addr(uint32_t base, int row0, int lane, int koff) {
    return base + (uint32_t)(row0 + (lane & 15)) * TSTR + (uint32_t)koff + ((lane >> 4) << 4);
}
__device__ __forceinline__ uint32_t b_addr(uint32_t base, int row0, int lane, int koff) {
    return base + (uint32_t)(row0 + (lane & 7) + ((lane >> 4) << 3)) * TSTR
                + (uint32_t)koff + (((lane >> 3) & 1) << 4);
}

// ---------------------------------------------------------------------------
// Kernel 0: split fp32 -> (hi, lo) bf16, 4 independent float4 per thread
// ---------------------------------------------------------------------------
constexpr int CV_THREADS_TOT = 73728;           // 288 blocks x 256
constexpr int CV_XN4 = XROWS * DD / 4;          // 262144
constexpr int CV_TOT4 = CV_XN4 + KK * DD / 4;   // 294912 = 4 * 73728 exactly

__global__ __launch_bounds__(256) void convert_kernel(
    const float* __restrict__ a, const float* __restrict__ b, const float* __restrict__ feats)
{
    const int t = blockIdx.x * 256 + threadIdx.x;

    float4 v[4];
    int base[4];
    bool isX[4];
#pragma unroll
    for (int k = 0; k < 4; k++) {
        const int i4 = t + k * CV_THREADS_TOT;
        if (i4 < CV_XN4) {
            base[k] = i4 * 4;
            isX[k] = true;
            v[k] = (base[k] < NA * DD)
                 ? *reinterpret_cast<const float4*>(a + base[k])
                 : *reinterpret_cast<const float4*>(b + base[k] - NA * DD);
        } else {
            base[k] = (i4 - CV_XN4) * 4;
            isX[k] = false;
            v[k] = *reinterpret_cast<const float4*>(feats + base[k]);
        }
    }
#pragma unroll
    for (int k = 0; k < 4; k++) {
        float xs[4] = {v[k].x, v[k].y, v[k].z, v[k].w};
        __nv_bfloat16 hs[4], ls[4];
#pragma unroll
        for (int i = 0; i < 4; i++) {
            hs[i] = __float2bfloat16(xs[i]);
            ls[i] = __float2bfloat16(xs[i] - __bfloat162float(hs[i]));
        }
        __nv_bfloat16* H = isX[k] ? g_Xh : g_Fh;
        __nv_bfloat16* L = isX[k] ? g_Xl : g_Fl;
        *reinterpret_cast<__nv_bfloat162*>(H + base[k])     = __nv_bfloat162(hs[0], hs[1]);
        *reinterpret_cast<__nv_bfloat162*>(H + base[k] + 2) = __nv_bfloat162(hs[2], hs[3]);
        *reinterpret_cast<__nv_bfloat162*>(L + base[k])     = __nv_bfloat162(ls[0], ls[1]);
        *reinterpret_cast<__nv_bfloat162*>(L + base[k] + 2) = __nv_bfloat162(ls[2], ls[3]);
    }
}

// ---------------------------------------------------------------------------
// Stage 1: C[2048x256] = X · F^T  (XhFh + XhFl + XlFh)
// Tile 64x64, k-chunk 64, 3 smem buffers, depth-2 cp.async, 1 sync/chunk.
// grid (4, 32), 256 threads, warp tile 16x32.
// ---------------------------------------------------------------------------
constexpr uint32_t S1_ARR = 64 * TSTR;          // 9216 per array
constexpr uint32_t S1_BUF = 4 * S1_ARR;         // 36864 (Xh, Xl, Fh, Fl)
constexpr int S1_SMEM = 3 * S1_BUF;             // 110592

__global__ __launch_bounds__(256) void stage1_mma()
{
    extern __shared__ char dsm[];
    const uint32_t sb = smem_u32(dsm);

    const int tid = threadIdx.x;
    const int lane = tid & 31;
    const int wid = tid >> 5;
    const int wm = wid & 3;          // 4 warp rows x 16
    const int wn = wid >> 2;         // 2 warp cols x 32

    const int m0 = blockIdx.y * 64;
    const int n0 = blockIdx.x * 64;

    const __nv_bfloat16* srcs[4] = {
        g_Xh + (size_t)m0 * DD, g_Xl + (size_t)m0 * DD,
        g_Fh + (size_t)n0 * DD, g_Fl + (size_t)n0 * DD };

    auto load_chunk = [&](int ch, uint32_t buf) {
        const int d0 = ch * 64;
        // 4 arrays x 64 rows x 8 x 16B = 2048 cp16 -> 8 per thread
#pragma unroll
        for (int u = 0; u < 8; u++) {
            const int vv = tid + u * 256;
            const int arr = vv >> 9, rem = vv & 511;
            const int r = rem >> 3, s = rem & 7;
            cp16(buf + (uint32_t)arr * S1_ARR + (uint32_t)r * TSTR + (uint32_t)(s << 4),
                 srcs[arr] + (size_t)r * DD + d0 + s * 8);
        }
        cp_commit();
    };

    constexpr int NCH = DD / 64;   // 8
    load_chunk(0, sb);
    load_chunk(1, sb + S1_BUF);

    float acc[4][4] = {};

    for (int ch = 0; ch < NCH; ch++) {
        if (ch + 1 < NCH) cp_wait1(); else cp_wait0();
        __syncthreads();
        if (ch + 2 < NCH) load_chunk(ch + 2, sb + (uint32_t)((ch + 2) % 3) * S1_BUF);

        const uint32_t bb = sb + (uint32_t)(ch % 3) * S1_BUF;
        const uint32_t bXh = bb, bXl = bb + S1_ARR, bFh = bb + 2 * S1_ARR, bFl = bb + 3 * S1_ARR;
#pragma unroll
        for (int ks = 0; ks < 4; ks++) {
            const int koff = ks * 32;
            uint32_t ah[4], al[4], fh[2][4], fl[2][4];
            ldm_x4(ah, a_addr(bXh, wm * 16, lane, koff));
            ldm_x4(al, a_addr(bXl, wm * 16, lane, koff));
#pragma unroll
            for (int p = 0; p < 2; p++) {
                ldm_x4(fh[p], b_addr(bFh, wn * 32 + p * 16, lane, koff));
                ldm_x4(fl[p], b_addr(bFl, wn * 32 + p * 16, lane, koff));
            }
#pragma unroll
            for (int nt = 0; nt < 4; nt++) {
                const uint32_t* bh = &fh[nt >> 1][(nt & 1) * 2];
                const uint32_t* bl = &fl[nt >> 1][(nt & 1) * 2];
                mma_bf16(acc[nt], ah, bh);
                mma_bf16(acc[nt], ah, bl);
                mma_bf16(acc[nt], al, bh);
            }
        }
    }

    // Epilogue: a-rows -> Ph = fp16(relu(v)); b-rows -> Mb = fp16(v<=0)
    const bool isA = (m0 < NA);
#pragma unroll
    for (int nt = 0; nt < 4; nt++)
#pragma unroll
        for (int h = 0; h < 2; h++) {
            const int grow = m0 + wm * 16 + (lane >> 2) + h * 8;
            const int col  = n0 + wn * 32 + nt * 8 + (lane & 3) * 2;
            const float v0 = acc[nt][h * 2 + 0];
            const float v1 = acc[nt][h * 2 + 1];
            if (isA) {
                const size_t idx = (size_t)grow * KK + col;
                *reinterpret_cast<__half2*>(g_Ph + idx) =
                    __half2(__float2half(fmaxf(v0, 0.0f)), __float2half(fmaxf(v1, 0.0f)));
            } else {
                const size_t idx = (size_t)(grow - NA) * KK + col;
                *reinterpret_cast<__half2*>(g_Mb + idx) =
                    __half2(__float2half(v0 <= 0.0f ? 1.0f : 0.0f),
                            __float2half(v1 <= 0.0f ? 1.0f : 0.0f));
            }
        }
}

// ---------------------------------------------------------------------------
// Stage 2: out[1024x1024] = Ph · Mb^T (fp16 operands, fp32 accum)
// Tile 64x64, k-chunk 64, 3 buffers, 1 sync/chunk. grid (16,16), 256 thr.
// ---------------------------------------------------------------------------
constexpr uint32_t S2_ARR = 64 * TSTR;          // 9216
constexpr uint32_t S2_BUF = 2 * S2_ARR;         // 18432 (Ph, Mb)
constexpr int S2_SMEM = 3 * S2_BUF;             // 55296

__global__ __launch_bounds__(256) void stage2_mma(float* __restrict__ out)
{
    extern __shared__ char dsm[];
    const uint32_t sb = smem_u32(dsm);

    const int tid = threadIdx.x;
    const int lane = tid & 31;
    const int wid = tid >> 5;
    const int wm = wid & 3;          // 4 warp rows x 16
    const int wn = wid >> 2;         // 2 warp cols x 32

    const int i0 = blockIdx.y * 64;
    const int j0 = blockIdx.x * 64;

    const __half* srcs[2] = { g_Ph + (size_t)i0 * KK, g_Mb + (size_t)j0 * KK };

    auto load_chunk = [&](int ch, uint32_t buf) {
        const int k0 = ch * 64;
        // 2 arrays x 64 rows x 8 x 16B = 1024 cp16 -> 4 per thread
#pragma unroll
        for (int u = 0; u < 4; u++) {
            const int vv = tid + u * 256;
            const int arr = vv >> 9, rem = vv & 511;
            const int r = rem >> 3, s = rem & 7;
            cp16(buf + (uint32_t)arr * S2_ARR + (uint32_t)r * TSTR + (uint32_t)(s << 4),
                 srcs[arr] + (size_t)r * KK + k0 + s * 8);
        }
        cp_commit();
    };

    constexpr int NCH = KK / 64;   // 4
    load_chunk(0, sb);
    load_chunk(1, sb + S2_BUF);

    float acc[4][4] = {};

    for (int ch = 0; ch < NCH; ch++) {
        if (ch + 1 < NCH) cp_wait1(); else cp_wait0();
        __syncthreads();
        if (ch + 2 < NCH) load_chunk(ch + 2, sb + (uint32_t)((ch + 2) % 3) * S2_BUF);

        const uint32_t bb = sb + (uint32_t)(ch % 3) * S2_BUF;
        const uint32_t bPh = bb, bMb = bb + S2_ARR;
#pragma unroll
        for (int ks = 0; ks < 4; ks++) {
            const int koff = ks * 32;
            uint32_t ph[4], mb[2][4];
            ldm_x4(ph, a_addr(bPh, wm * 16, lane, koff));
#pragma unroll
            for (int p = 0; p < 2; p++)
                ldm_x4(mb[p], b_addr(bMb, wn * 32 + p * 16, lane, koff));
#pragma unroll
            for (int nt = 0; nt < 4; nt++)
                mma_f16(acc[nt], ph, &mb[nt >> 1][(nt & 1) * 2]);
        }
    }

#pragma unroll
    for (int nt = 0; nt < 4; nt++)
#pragma unroll
        for (int h = 0; h < 2; h++) {
            const int row = i0 + wm * 16 + (lane >> 2) + h * 8;
            const int col = j0 + wn * 32 + nt * 8 + (lane & 3) * 2;
            *reinterpret_cast<float2*>(out + (size_t)row * NB + col) =
                make_float2(acc[nt][h * 2 + 0], acc[nt][h * 2 + 1]);
        }
}

// ---------------------------------------------------------------------------
extern "C" void kernel_launch(void* const* d_in, const int* in_sizes, int n_in,
                              void* d_out, int out_size)
{
    const float* a     = (const float*)d_in[0];
    const float* b     = (const float*)d_in[1];
    const float* feats = (const float*)d_in[2];
    float* out = (float*)d_out;
    (void)in_sizes; (void)n_in; (void)out_size;

    cudaFuncSetAttribute(stage1_mma, cudaFuncAttributeMaxDynamicSharedMemorySize, S1_SMEM);
    cudaFuncSetAttribute(stage2_mma, cudaFuncAttributeMaxDynamicSharedMemorySize, S2_SMEM);

    convert_kernel<<<288, 256>>>(a, b, feats);
    stage1_mma<<<dim3(4, 32), 256, S1_SMEM>>>();
    stage2_mma<<<dim3(16, 16), 256, S2_SMEM>>>(out);
}